// round 1
// baseline (speedup 1.0000x reference)
#include <cuda_runtime.h>
#include <math.h>

#define BATCH   16
#define DMODEL  4096
#define NH      32
#define NKV     8
#define DK      128
#define GQ      4          // NH / NKV
#define MAXBLK  256
#define SPLITS  8
#define TT      64         // tokens per attention tile

// ---------------- scratch (static device globals; no allocation) ------------
__device__ float g_q  [BATCH * DMODEL];          // Q after proj+rope  [b][head*128+d]
__device__ float g_k  [BATCH * NKV * DK];        // new K after rope
__device__ float g_v  [BATCH * NKV * DK];        // new V
__device__ float g_att[BATCH * DMODEL];          // attention output (pre W_O)
__device__ float g_po [BATCH * NKV * SPLITS * GQ * DK];
__device__ float g_pm [BATCH * NKV * SPLITS * GQ];
__device__ float g_pl [BATCH * NKV * SPLITS * GQ];

// ---------------- batched GEMV: out[b][r] = dot(W[r,:], x[b,:]) -------------
// grid.x = rows/16, block = 256 (8 warps, 2 rows per warp), K = DMODEL fixed.
__global__ __launch_bounds__(256) void gemv16(const float* __restrict__ W,
                                              const float* __restrict__ x,
                                              float* __restrict__ out, int ld)
{
    __shared__ __align__(16) float xs[BATCH][512];
    const int tid  = threadIdx.x;
    const int lane = tid & 31;
    const int wid  = tid >> 5;
    const int r0   = blockIdx.x * 16 + wid * 2;
    const float* w0 = W + (size_t)r0 * DMODEL;
    const float* w1 = w0 + DMODEL;

    float acc0[16], acc1[16];
#pragma unroll
    for (int b = 0; b < 16; b++) { acc0[b] = 0.f; acc1[b] = 0.f; }

    const float4* xg  = (const float4*)x;
    float4*       xs4 = (float4*)&xs[0][0];

    for (int t = 0; t < DMODEL; t += 512) {
        __syncthreads();
#pragma unroll
        for (int i = 0; i < 8; i++) {
            int f  = tid + i * 256;          // 0..2047 float4s
            int b  = f >> 7;
            int kk = f & 127;
            xs4[f] = xg[b * (DMODEL / 4) + (t >> 2) + kk];
        }
        __syncthreads();
#pragma unroll
        for (int it = 0; it < 4; it++) {
            int k = t + it * 128 + lane * 4;
            float4 a = *(const float4*)(w0 + k);
            float4 c = *(const float4*)(w1 + k);
#pragma unroll
            for (int b = 0; b < 16; b++) {
                float4 xv = *(const float4*)&xs[b][it * 128 + lane * 4];
                acc0[b] += a.x * xv.x + a.y * xv.y + a.z * xv.z + a.w * xv.w;
                acc1[b] += c.x * xv.x + c.y * xv.y + c.z * xv.z + c.w * xv.w;
            }
        }
    }
#pragma unroll
    for (int b = 0; b < 16; b++) {
#pragma unroll
        for (int off = 16; off; off >>= 1) {
            acc0[b] += __shfl_xor_sync(0xffffffffu, acc0[b], off);
            acc1[b] += __shfl_xor_sync(0xffffffffu, acc1[b], off);
        }
    }
    if (lane == 0) {
#pragma unroll
        for (int b = 0; b < 16; b++) {
            out[(size_t)b * ld + r0]     = acc0[b];
            out[(size_t)b * ld + r0 + 1] = acc1[b];
        }
    }
}

// ---------------- RoPE on q (32 heads) and k_new (8 heads) ------------------
__global__ void rope_kernel(const int* __restrict__ positions)
{
    int b = blockIdx.x;
    float pos = (float)positions[b];
    const float L2T_64 = 13.287712379549449f / 64.f;   // log2(10000)/64
    for (int i = threadIdx.x; i < (NH + NKV) * 64; i += blockDim.x) {
        int row = i >> 6;
        int d   = i & 63;
        float* p = (row < NH) ? (g_q + b * DMODEL + row * DK)
                              : (g_k + b * NKV * DK + (row - NH) * DK);
        float inv = exp2f(-(float)d * L2T_64);
        float ang = pos * inv;
        float s, c;
        sincosf(ang, &s, &c);
        float x0 = p[d], x1 = p[d + 64];
        p[d]      = x0 * c - x1 * s;
        p[d + 64] = x1 * c + x0 * s;
    }
}

// ---------------- flash-decode attention, split over sequence ---------------
// grid = (SPLITS, NKV, BATCH), block = 256
__global__ __launch_bounds__(256) void attn_kernel(
    const float* __restrict__ k_pool, const float* __restrict__ v_pool,
    const int* __restrict__ positions, const int* __restrict__ block_table)
{
    __shared__ __align__(16) float Vs[TT][DK];
    __shared__ float ss[GQ][TT];
    __shared__ float ps[GQ][TT];
    __shared__ float salpha[GQ];
    __shared__ __align__(16) float qs[GQ * DK];

    const int split = blockIdx.x, h = blockIdx.y, b = blockIdx.z;
    const int tid = threadIdx.x, lane = tid & 31, wid = tid >> 5;

    const int pos = positions[b];
    const int seq = pos + 1;
    const int chunk = (seq + SPLITS - 1) / SPLITS;
    const int s0 = split * chunk;
    const int s1 = min(s0 + chunk, seq);

    qs[tid]       = g_q[b * DMODEL + h * GQ * DK + tid];
    qs[tid + 256] = g_q[b * DMODEL + h * GQ * DK + tid + 256];
    __syncthreads();

    const float scale = 0.08838834764831845f;  // 1/sqrt(128)
    float m_run = -INFINITY, l_run = 0.f;
    const int g2 = tid >> 6;            // 0..3 (epilogue group)
    const int d0 = (tid & 63) * 2;
    float o0 = 0.f, o1 = 0.f;

    for (int t0 = s0; t0 < s1; t0 += TT) {
        const int nv = min(s1 - t0, TT);
        // ---- phase A: scores + stage V (each warp owns 8 tokens) ----
        int jend = min(wid * 8 + 8, nv);
        for (int j = wid * 8; j < jend; j++) {
            int gt   = t0 + j;
            int page = block_table[b * MAXBLK + (gt >> 4)];
            long base = (((long)page * 16 + (gt & 15)) * NKV + h) * DK;
            const float* kp = k_pool + base;
            const float* vp = v_pool + base;
            if (gt == pos) {
                kp = g_k + (b * NKV + h) * DK;
                vp = g_v + (b * NKV + h) * DK;
            }
            float4 kv = *(const float4*)(kp + lane * 4);
            float4 vv = *(const float4*)(vp + lane * 4);
            *(float4*)&Vs[j][lane * 4] = vv;
            float4 q0 = *(const float4*)&qs[0 * DK + lane * 4];
            float4 q1 = *(const float4*)&qs[1 * DK + lane * 4];
            float4 q2 = *(const float4*)&qs[2 * DK + lane * 4];
            float4 q3 = *(const float4*)&qs[3 * DK + lane * 4];
            float p0 = kv.x * q0.x + kv.y * q0.y + kv.z * q0.z + kv.w * q0.w;
            float p1 = kv.x * q1.x + kv.y * q1.y + kv.z * q1.z + kv.w * q1.w;
            float p2 = kv.x * q2.x + kv.y * q2.y + kv.z * q2.z + kv.w * q2.w;
            float p3 = kv.x * q3.x + kv.y * q3.y + kv.z * q3.z + kv.w * q3.w;
#pragma unroll
            for (int off = 16; off; off >>= 1) {
                p0 += __shfl_xor_sync(0xffffffffu, p0, off);
                p1 += __shfl_xor_sync(0xffffffffu, p1, off);
                p2 += __shfl_xor_sync(0xffffffffu, p2, off);
                p3 += __shfl_xor_sync(0xffffffffu, p3, off);
            }
            if (lane == 0) {
                ss[0][j] = p0 * scale;
                ss[1][j] = p1 * scale;
                ss[2][j] = p2 * scale;
                ss[3][j] = p3 * scale;
            }
        }
        __syncthreads();
        // ---- phase B1: online softmax update (warps 0..3, one per g) ----
        if (wid < 4) {
            int g = wid;
            float v0 = (lane      < nv) ? ss[g][lane]      : -INFINITY;
            float v1 = (lane + 32 < nv) ? ss[g][lane + 32] : -INFINITY;
            float mt = fmaxf(v0, v1);
#pragma unroll
            for (int off = 16; off; off >>= 1)
                mt = fmaxf(mt, __shfl_xor_sync(0xffffffffu, mt, off));
            float m_new = fmaxf(m_run, mt);
            float alpha = __expf(m_run - m_new);
            float e0 = __expf(v0 - m_new);
            float e1 = __expf(v1 - m_new);
            ps[g][lane]      = e0;
            ps[g][lane + 32] = e1;
            float sum = e0 + e1;
#pragma unroll
            for (int off = 16; off; off >>= 1)
                sum += __shfl_xor_sync(0xffffffffu, sum, off);
            l_run = l_run * alpha + sum;
            m_run = m_new;
            if (lane == 0) salpha[g] = alpha;
        }
        __syncthreads();
        // ---- phase B2: accumulate O (all 256 threads, 2 dims each) ----
        {
            float alpha = salpha[g2];
            o0 *= alpha;
            o1 *= alpha;
            for (int j = 0; j < nv; j++) {
                float  p = ps[g2][j];
                float2 v = *(const float2*)&Vs[j][d0];
                o0 += p * v.x;
                o1 += p * v.y;
            }
        }
        __syncthreads();
    }

    const int pidx = (b * NKV + h) * SPLITS + split;
    g_po[pidx * (GQ * DK) + g2 * DK + d0]     = o0;
    g_po[pidx * (GQ * DK) + g2 * DK + d0 + 1] = o1;
    if (wid < 4 && lane == 0) {
        g_pm[pidx * GQ + wid] = m_run;
        g_pl[pidx * GQ + wid] = l_run;
    }
}

// ---------------- combine split partials -> g_att ---------------------------
// grid = BATCH*NKV, block = 128
__global__ void combine_kernel()
{
    int h = blockIdx.x & (NKV - 1);
    int b = blockIdx.x / NKV;
    int d = threadIdx.x;
    int base = (b * NKV + h) * SPLITS;
    for (int g = 0; g < GQ; g++) {
        float M = -INFINITY;
#pragma unroll
        for (int s = 0; s < SPLITS; s++)
            M = fmaxf(M, g_pm[(base + s) * GQ + g]);
        float L = 0.f, o = 0.f;
#pragma unroll
        for (int s = 0; s < SPLITS; s++) {
            float e = expf(g_pm[(base + s) * GQ + g] - M);
            L += g_pl[(base + s) * GQ + g] * e;
            o += e * g_po[(base + s) * (GQ * DK) + g * DK + d];
        }
        g_att[b * DMODEL + (h * GQ + g) * DK + d] = o / L;
    }
}

// ---------------- host launcher ---------------------------------------------
extern "C" void kernel_launch(void* const* d_in, const int* in_sizes, int n_in,
                              void* d_out, int out_size)
{
    const float* hs = (const float*)d_in[0];
    const float* WQ = (const float*)d_in[1];
    const float* WK = (const float*)d_in[2];
    const float* WV = (const float*)d_in[3];
    const float* WO = (const float*)d_in[4];
    const float* kp = (const float*)d_in[5];
    const float* vp = (const float*)d_in[6];
    const int*   ps = (const int*)d_in[7];
    const int*   bt = (const int*)d_in[8];
    float* out = (float*)d_out;

    float *gq, *gk, *gv, *gatt;
    cudaGetSymbolAddress((void**)&gq,   g_q);
    cudaGetSymbolAddress((void**)&gk,   g_k);
    cudaGetSymbolAddress((void**)&gv,   g_v);
    cudaGetSymbolAddress((void**)&gatt, g_att);

    // QKV projections
    gemv16<<<DMODEL / 16, 256>>>(WQ, hs, gq, DMODEL);
    gemv16<<<(NKV * DK) / 16, 256>>>(WK, hs, gk, NKV * DK);
    gemv16<<<(NKV * DK) / 16, 256>>>(WV, hs, gv, NKV * DK);
    // RoPE on q and k_new
    rope_kernel<<<BATCH, 256>>>(ps);
    // split attention + combine
    attn_kernel<<<dim3(SPLITS, NKV, BATCH), 256>>>(kp, vp, ps, bt);
    combine_kernel<<<BATCH * NKV, 128>>>();
    // output projection
    gemv16<<<DMODEL / 16, 256>>>(WO, gatt, out, DMODEL);
}